// round 1
// baseline (speedup 1.0000x reference)
#include <cuda_runtime.h>
#include <cuda_bf16.h>

#define NN 100000
#define NE 3200000
#define DD 128

// Scratch (allocation-free rule: __device__ globals)
__device__ int   g_deg[NN];
__device__ int   g_start[NN];
__device__ int   g_cursor[NN];
__device__ float g_dinv[NN];
__device__ int   g_col[NE];
__device__ float g_norm[NE];
__device__ float g_xl[(size_t)NN * DD];

// ---------------------------------------------------------------- zero deg
__global__ void k_zero() {
    int i = blockIdx.x * blockDim.x + threadIdx.x;
    if (i < NN) g_deg[i] = 0;
}

// ---------------------------------------------------------------- degree count
__global__ void k_count(const int* __restrict__ row) {
    int e = blockIdx.x * blockDim.x + threadIdx.x;
    if (e < NE) atomicAdd(&g_deg[row[e]], 1);
}

// ---------------------------------------------------------------- exclusive scan (single block) + dinv
__global__ void k_scan() {
    __shared__ int s[1024];
    const int CH = (NN + 1023) / 1024;  // 98 items per thread
    int t = threadIdx.x;
    int base = t * CH;

    int sum = 0;
    for (int i = 0; i < CH; i++) {
        int idx = base + i;
        if (idx < NN) sum += g_deg[idx];
    }
    s[t] = sum;
    __syncthreads();
    // Hillis-Steele inclusive scan over 1024 thread sums
    for (int off = 1; off < 1024; off <<= 1) {
        int v = s[t];
        if (t >= off) v += s[t - off];
        __syncthreads();
        s[t] = v;
        __syncthreads();
    }
    int run = (t == 0) ? 0 : s[t - 1];
    for (int i = 0; i < CH; i++) {
        int idx = base + i;
        if (idx < NN) {
            int d = g_deg[idx];
            g_start[idx]  = run;
            g_cursor[idx] = run;
            g_dinv[idx]   = (d > 0) ? rsqrtf((float)d) : 0.0f;
            run += d;
        }
    }
}

// ---------------------------------------------------------------- CSR bucket scatter
__global__ void k_scatter(const int* __restrict__ row, const int* __restrict__ col) {
    int e = blockIdx.x * blockDim.x + threadIdx.x;
    if (e < NE) {
        int r = row[e];
        int c = col[e];
        int pos = atomicAdd(&g_cursor[r], 1);
        g_col[pos]  = c;
        g_norm[pos] = g_dinv[r] * g_dinv[c];
    }
}

// ---------------------------------------------------------------- xl = x @ W^T + b
// BM=64 rows per block, full N=128 per block, K chunked by 32.
// 256 threads: tx = n-group (4 cols each), ty = row-group (8 rows each).
#define BM 64
#define BK 32
__global__ __launch_bounds__(256) void k_gemm(const float* __restrict__ x,
                                              const float* __restrict__ W,
                                              const float* __restrict__ b) {
    __shared__ float Xs[BM][BK + 1];    // [row][k], +1 pad
    __shared__ float Wt[BK][132];       // [k][n] transposed W chunk, stride 132 keeps f4 16B-aligned

    int t  = threadIdx.x;
    int tx = t & 31;    // 0..31 -> n0 = 4*tx
    int ty = t >> 5;    // 0..7
    int row0 = blockIdx.x * BM;
    int n0 = tx * 4;

    float acc[8][4];
#pragma unroll
    for (int i = 0; i < 8; i++)
#pragma unroll
        for (int j = 0; j < 4; j++) acc[i][j] = 0.0f;

    for (int k0 = 0; k0 < DD; k0 += BK) {
        // Load X tile: 64 x 32, coalesced over k
#pragma unroll
        for (int i = 0; i < 8; i++) {
            int m = ty + i * 8;             // 0..63
            int r = row0 + m;
            if (r >= NN) r = NN - 1;        // clamp (values unused on store)
            Xs[m][tx] = x[(size_t)r * DD + k0 + tx];
        }
        // Load + transpose W chunk: Wt[k][n] = W[n][k0+k]
#pragma unroll
        for (int i = 0; i < 16; i++) {
            int n = ty + i * 8;             // 0..127
            Wt[tx][n] = W[n * DD + k0 + tx];
        }
        __syncthreads();

#pragma unroll
        for (int kk = 0; kk < BK; kk++) {
            float4 wv = *(const float4*)&Wt[kk][n0];   // conflict-free f4
#pragma unroll
            for (int i = 0; i < 8; i++) {
                float a = Xs[ty * 8 + i][kk];          // warp-broadcast
                acc[i][0] += a * wv.x;
                acc[i][1] += a * wv.y;
                acc[i][2] += a * wv.z;
                acc[i][3] += a * wv.w;
            }
        }
        __syncthreads();
    }

    float4 bias = *(const float4*)&b[n0];
#pragma unroll
    for (int i = 0; i < 8; i++) {
        int r = row0 + ty * 8 + i;
        if (r < NN) {
            float4 o;
            o.x = acc[i][0] + bias.x;
            o.y = acc[i][1] + bias.y;
            o.z = acc[i][2] + bias.z;
            o.w = acc[i][3] + bias.w;
            *(float4*)&g_xl[(size_t)r * DD + n0] = o;
        }
    }
}

// ---------------------------------------------------------------- warp-per-node aggregation
__global__ __launch_bounds__(256) void k_agg(float* __restrict__ out) {
    int wid  = (blockIdx.x * blockDim.x + threadIdx.x) >> 5;
    int lane = threadIdx.x & 31;
    if (wid >= NN) return;

    int s = g_start[wid];
    int d = g_deg[wid];

    float4 acc = make_float4(0.f, 0.f, 0.f, 0.f);

    for (int e0 = 0; e0 < d; e0 += 32) {
        int idx = e0 + lane;
        int   c  = 0;
        float nv = 0.0f;
        if (idx < d) {
            c  = g_col[s + idx];
            nv = g_norm[s + idx];
        }
        int m = min(32, d - e0);
#pragma unroll 4
        for (int j = 0; j < m; j++) {
            int   cj = __shfl_sync(0xffffffffu, c, j);
            float nj = __shfl_sync(0xffffffffu, nv, j);
            float4 v = *(const float4*)&g_xl[(size_t)cj * DD + lane * 4];
            acc.x += nj * v.x;
            acc.y += nj * v.y;
            acc.z += nj * v.z;
            acc.w += nj * v.w;
        }
    }
    *(float4*)&out[(size_t)wid * DD + lane * 4] = acc;
}

// ---------------------------------------------------------------- launch
extern "C" void kernel_launch(void* const* d_in, const int* in_sizes, int n_in,
                              void* d_out, int out_size) {
    const float* x  = (const float*)d_in[0];
    const int*   ei = (const int*)d_in[1];
    const float* W  = (const float*)d_in[2];
    const float* b  = (const float*)d_in[3];
    float* out = (float*)d_out;

    const int* row = ei;
    const int* col = ei + NE;

    k_zero   <<<(NN + 255) / 256, 256>>>();
    k_count  <<<(NE + 255) / 256, 256>>>(row);
    k_scan   <<<1, 1024>>>();
    k_gemm   <<<(NN + BM - 1) / BM, 256>>>(x, W, b);
    k_scatter<<<(NE + 255) / 256, 256>>>(row, col);
    k_agg    <<<((size_t)NN * 32 + 255) / 256, 256>>>(out);
}

// round 2
// speedup vs baseline: 2.1001x; 2.1001x over previous
#include <cuda_runtime.h>
#include <cuda_bf16.h>

#define NN 100000
#define NE 3200000
#define DD 128

#define SCAN_B 1024
#define NBLK ((NN + SCAN_B - 1) / SCAN_B)   // 98

// Scratch (__device__ globals — allocation-free rule)
__device__ int   g_deg[NN];
__device__ int   g_start[NN];
__device__ int   g_cursor[NN];
__device__ float g_dinv[NN];
__device__ int   g_bsum[NBLK];
__device__ int   g_boff[NBLK];
struct __align__(8) EdgeRec { int c; float n; };
__device__ EdgeRec g_edge[NE];
__device__ float g_xl[(size_t)NN * DD];

// ---------------------------------------------------------------- zero deg
__global__ void k_zero() {
    int i = blockIdx.x * blockDim.x + threadIdx.x;
    if (i < NN) g_deg[i] = 0;
}

// ---------------------------------------------------------------- degree count (4 edges/thread)
__global__ void k_count(const int* __restrict__ row) {
    int t = blockIdx.x * blockDim.x + threadIdx.x;
    int e = t * 4;
    if (e + 4 <= NE) {
        int4 r4 = *(const int4*)&row[e];
        atomicAdd(&g_deg[r4.x], 1);
        atomicAdd(&g_deg[r4.y], 1);
        atomicAdd(&g_deg[r4.z], 1);
        atomicAdd(&g_deg[r4.w], 1);
    } else {
        for (int i = e; i < NE; i++) atomicAdd(&g_deg[row[i]], 1);
    }
}

// ---------------------------------------------------------------- scan stage 1: per-block sums
__global__ __launch_bounds__(SCAN_B) void k_scan1() {
    __shared__ int s[SCAN_B];
    int idx = blockIdx.x * SCAN_B + threadIdx.x;
    int v = (idx < NN) ? g_deg[idx] : 0;
    s[threadIdx.x] = v;
    __syncthreads();
    for (int off = SCAN_B / 2; off > 0; off >>= 1) {
        if (threadIdx.x < off) s[threadIdx.x] += s[threadIdx.x + off];
        __syncthreads();
    }
    if (threadIdx.x == 0) g_bsum[blockIdx.x] = s[0];
}

// ---------------------------------------------------------------- scan stage 2: scan block sums (1 block)
__global__ void k_scan2() {
    __shared__ int s[128];
    int t = threadIdx.x;
    int v = (t < NBLK) ? g_bsum[t] : 0;
    s[t] = v;
    __syncthreads();
    for (int off = 1; off < 128; off <<= 1) {
        int x = s[t];
        if (t >= off) x += s[t - off];
        __syncthreads();
        s[t] = x;
        __syncthreads();
    }
    if (t < NBLK) g_boff[t] = (t == 0) ? 0 : s[t - 1];
}

// ---------------------------------------------------------------- scan stage 3: local scan + offset + dinv
__global__ __launch_bounds__(SCAN_B) void k_scan3() {
    __shared__ int s[SCAN_B];
    int t = threadIdx.x;
    int idx = blockIdx.x * SCAN_B + t;
    int d = (idx < NN) ? g_deg[idx] : 0;
    s[t] = d;
    __syncthreads();
    for (int off = 1; off < SCAN_B; off <<= 1) {
        int x = s[t];
        if (t >= off) x += s[t - off];
        __syncthreads();
        s[t] = x;
        __syncthreads();
    }
    if (idx < NN) {
        int start = g_boff[blockIdx.x] + s[t] - d;   // exclusive
        g_start[idx]  = start;
        g_cursor[idx] = start;
        g_dinv[idx]   = (d > 0) ? rsqrtf((float)d) : 0.0f;
    }
}

// ---------------------------------------------------------------- CSR scatter, packed 8B record
__global__ void k_scatter(const int* __restrict__ row, const int* __restrict__ col) {
    int e = blockIdx.x * blockDim.x + threadIdx.x;
    if (e < NE) {
        int r = row[e];
        int c = col[e];
        int pos = atomicAdd(&g_cursor[r], 1);
        EdgeRec rec;
        rec.c = c;
        rec.n = g_dinv[r] * g_dinv[c];
        g_edge[pos] = rec;                  // single STG.64
    }
}

// ---------------------------------------------------------------- xl = x @ W^T + b  (f32x2 packed FMA)
#define BM 64
#define BK 32
__global__ __launch_bounds__(256) void k_gemm(const float* __restrict__ x,
                                              const float* __restrict__ W,
                                              const float* __restrict__ b) {
    __shared__ float Xs[BM][BK + 1];
    __shared__ float Wt[BK][132];

    int t  = threadIdx.x;
    int tx = t & 31;
    int ty = t >> 5;
    int row0 = blockIdx.x * BM;
    int n0 = tx * 4;

    unsigned long long acc[8][2];
#pragma unroll
    for (int i = 0; i < 8; i++) { acc[i][0] = 0ull; acc[i][1] = 0ull; }

    for (int k0 = 0; k0 < DD; k0 += BK) {
#pragma unroll
        for (int i = 0; i < 8; i++) {
            int m = ty + i * 8;
            int r = row0 + m;
            if (r >= NN) r = NN - 1;
            Xs[m][tx] = x[(size_t)r * DD + k0 + tx];
        }
#pragma unroll
        for (int i = 0; i < 16; i++) {
            int n = ty + i * 8;
            Wt[tx][n] = W[n * DD + k0 + tx];
        }
        __syncthreads();

#pragma unroll
        for (int kk = 0; kk < BK; kk++) {
            float4 wv = *(const float4*)&Wt[kk][n0];
            unsigned long long wxy, wzw;
            asm("mov.b64 %0, {%1, %2};" : "=l"(wxy) : "f"(wv.x), "f"(wv.y));
            asm("mov.b64 %0, {%1, %2};" : "=l"(wzw) : "f"(wv.z), "f"(wv.w));
#pragma unroll
            for (int i = 0; i < 8; i++) {
                float a = Xs[ty * 8 + i][kk];
                unsigned long long a2;
                asm("mov.b64 %0, {%1, %1};" : "=l"(a2) : "f"(a));
                asm("fma.rn.f32x2 %0, %1, %2, %0;" : "+l"(acc[i][0]) : "l"(a2), "l"(wxy));
                asm("fma.rn.f32x2 %0, %1, %2, %0;" : "+l"(acc[i][1]) : "l"(a2), "l"(wzw));
            }
        }
        __syncthreads();
    }

    float4 bias = *(const float4*)&b[n0];
#pragma unroll
    for (int i = 0; i < 8; i++) {
        int r = row0 + ty * 8 + i;
        if (r < NN) {
            float ax, ay, az, aw;
            asm("mov.b64 {%0, %1}, %2;" : "=f"(ax), "=f"(ay) : "l"(acc[i][0]));
            asm("mov.b64 {%0, %1}, %2;" : "=f"(az), "=f"(aw) : "l"(acc[i][1]));
            float4 o;
            o.x = ax + bias.x;
            o.y = ay + bias.y;
            o.z = az + bias.z;
            o.w = aw + bias.w;
            *(float4*)&g_xl[(size_t)r * DD + n0] = o;
        }
    }
}

// ---------------------------------------------------------------- warp-per-node aggregation
// Broadcast int4 loads of packed edge records (2 edges per int4), gather float4, no shfl.
__global__ __launch_bounds__(256) void k_agg(float* __restrict__ out) {
    int wid  = (blockIdx.x * blockDim.x + threadIdx.x) >> 5;
    int lane = threadIdx.x & 31;
    if (wid >= NN) return;

    int s = g_start[wid];
    int d = g_deg[wid];

    float4 acc = make_float4(0.f, 0.f, 0.f, 0.f);
    const int4* ep = (const int4*)&g_edge[s];   // g_edge 8B-aligned; s*8 % 16 may be 8 — handle below
    // ensure 16B alignment: if s is odd, process one edge first
    int j = 0;
    if (s & 1) {
        if (d > 0) {
            EdgeRec e = g_edge[s];
            float4 v = *(const float4*)&g_xl[(size_t)e.c * DD + lane * 4];
            acc.x += e.n * v.x; acc.y += e.n * v.y; acc.z += e.n * v.z; acc.w += e.n * v.w;
            j = 1;
        }
        ep = (const int4*)&g_edge[s + 1];
    }

    for (; j + 4 <= d; j += 4) {
        int4 p0 = __ldg(&ep[0]);
        int4 p1 = __ldg(&ep[1]);
        ep += 2;
        int   c0 = p0.x; float n0 = __int_as_float(p0.y);
        int   c1 = p0.z; float n1 = __int_as_float(p0.w);
        int   c2 = p1.x; float n2 = __int_as_float(p1.y);
        int   c3 = p1.z; float n3 = __int_as_float(p1.w);
        float4 v0 = *(const float4*)&g_xl[(size_t)c0 * DD + lane * 4];
        float4 v1 = *(const float4*)&g_xl[(size_t)c1 * DD + lane * 4];
        float4 v2 = *(const float4*)&g_xl[(size_t)c2 * DD + lane * 4];
        float4 v3 = *(const float4*)&g_xl[(size_t)c3 * DD + lane * 4];
        acc.x += n0 * v0.x; acc.y += n0 * v0.y; acc.z += n0 * v0.z; acc.w += n0 * v0.w;
        acc.x += n1 * v1.x; acc.y += n1 * v1.y; acc.z += n1 * v1.z; acc.w += n1 * v1.w;
        acc.x += n2 * v2.x; acc.y += n2 * v2.y; acc.z += n2 * v2.z; acc.w += n2 * v2.w;
        acc.x += n3 * v3.x; acc.y += n3 * v3.y; acc.z += n3 * v3.z; acc.w += n3 * v3.w;
    }
    for (; j < d; j++) {
        EdgeRec e = g_edge[s + j];
        float4 v = *(const float4*)&g_xl[(size_t)e.c * DD + lane * 4];
        acc.x += e.n * v.x; acc.y += e.n * v.y; acc.z += e.n * v.z; acc.w += e.n * v.w;
    }
    *(float4*)&out[(size_t)wid * DD + lane * 4] = acc;
}

// ---------------------------------------------------------------- stream fork for GEMM overlap
static cudaStream_t g_s2;
static cudaEvent_t  g_evFork, g_evJoin;
static struct StreamInit {
    StreamInit() {
        cudaStreamCreateWithFlags(&g_s2, cudaStreamNonBlocking);
        cudaEventCreateWithFlags(&g_evFork, cudaEventDisableTiming);
        cudaEventCreateWithFlags(&g_evJoin, cudaEventDisableTiming);
    }
} g_streamInit;

// ---------------------------------------------------------------- launch
extern "C" void kernel_launch(void* const* d_in, const int* in_sizes, int n_in,
                              void* d_out, int out_size) {
    const float* x  = (const float*)d_in[0];
    const int*   ei = (const int*)d_in[1];
    const float* W  = (const float*)d_in[2];
    const float* b  = (const float*)d_in[3];
    float* out = (float*)d_out;

    const int* row = ei;
    const int* col = ei + NE;

    // Fork: GEMM on side stream, CSR build on main stream, join before agg.
    cudaEventRecord(g_evFork, 0);
    cudaStreamWaitEvent(g_s2, g_evFork, 0);
    k_gemm<<<(NN + BM - 1) / BM, 256, 0, g_s2>>>(x, W, b);
    cudaEventRecord(g_evJoin, g_s2);

    k_zero   <<<(NN + 255) / 256, 256>>>();
    k_count  <<<(NE / 4 + 255) / 256, 256>>>(row);
    k_scan1  <<<NBLK, SCAN_B>>>();
    k_scan2  <<<1, 128>>>();
    k_scan3  <<<NBLK, SCAN_B>>>();
    k_scatter<<<(NE + 255) / 256, 256>>>(row, col);

    cudaStreamWaitEvent(0, g_evJoin, 0);
    k_agg    <<<((size_t)NN * 32 + 255) / 256, 256>>>(out);
}

// round 3
// speedup vs baseline: 2.2139x; 1.0542x over previous
#include <cuda_runtime.h>
#include <cuda_bf16.h>
#include <cuda_fp16.h>

#define NN 100000
#define NE 3200000
#define DD 128

#define SCAN_B 1024
#define NBLK ((NN + SCAN_B - 1) / SCAN_B)   // 98

// Scratch (__device__ globals — allocation-free rule)
__device__ int   g_deg[NN];
__device__ int   g_start[NN];
__device__ int   g_cursor[NN];
__device__ float g_dinv[NN];
__device__ int   g_bsum[NBLK];
__device__ int   g_boff[NBLK];
struct __align__(8) EdgeRec { int c; float n; };
__device__ EdgeRec g_edge[NE];
__device__ __half g_xlh[(size_t)NN * DD];    // fp16 transformed features (gather operand)

// ---------------------------------------------------------------- zero deg
__global__ void k_zero() {
    int i = blockIdx.x * blockDim.x + threadIdx.x;
    if (i < NN) g_deg[i] = 0;
}

// ---------------------------------------------------------------- degree count (4 edges/thread)
__global__ void k_count(const int* __restrict__ row) {
    int t = blockIdx.x * blockDim.x + threadIdx.x;
    int e = t * 4;
    if (e + 4 <= NE) {
        int4 r4 = *(const int4*)&row[e];
        atomicAdd(&g_deg[r4.x], 1);
        atomicAdd(&g_deg[r4.y], 1);
        atomicAdd(&g_deg[r4.z], 1);
        atomicAdd(&g_deg[r4.w], 1);
    } else {
        for (int i = e; i < NE; i++) atomicAdd(&g_deg[row[i]], 1);
    }
}

// ---------------------------------------------------------------- scan stage 1: per-block sums
__global__ __launch_bounds__(SCAN_B) void k_scan1() {
    __shared__ int s[SCAN_B];
    int idx = blockIdx.x * SCAN_B + threadIdx.x;
    int v = (idx < NN) ? g_deg[idx] : 0;
    s[threadIdx.x] = v;
    __syncthreads();
    for (int off = SCAN_B / 2; off > 0; off >>= 1) {
        if (threadIdx.x < off) s[threadIdx.x] += s[threadIdx.x + off];
        __syncthreads();
    }
    if (threadIdx.x == 0) g_bsum[blockIdx.x] = s[0];
}

// ---------------------------------------------------------------- scan stage 2: scan block sums (1 block)
__global__ void k_scan2() {
    __shared__ int s[128];
    int t = threadIdx.x;
    int v = (t < NBLK) ? g_bsum[t] : 0;
    s[t] = v;
    __syncthreads();
    for (int off = 1; off < 128; off <<= 1) {
        int x = s[t];
        if (t >= off) x += s[t - off];
        __syncthreads();
        s[t] = x;
        __syncthreads();
    }
    if (t < NBLK) g_boff[t] = (t == 0) ? 0 : s[t - 1];
}

// ---------------------------------------------------------------- scan stage 3: local scan + offset + dinv
__global__ __launch_bounds__(SCAN_B) void k_scan3() {
    __shared__ int s[SCAN_B];
    int t = threadIdx.x;
    int idx = blockIdx.x * SCAN_B + t;
    int d = (idx < NN) ? g_deg[idx] : 0;
    s[t] = d;
    __syncthreads();
    for (int off = 1; off < SCAN_B; off <<= 1) {
        int x = s[t];
        if (t >= off) x += s[t - off];
        __syncthreads();
        s[t] = x;
        __syncthreads();
    }
    if (idx < NN) {
        int start = g_boff[blockIdx.x] + s[t] - d;   // exclusive
        g_start[idx]  = start;
        g_cursor[idx] = start;
        g_dinv[idx]   = (d > 0) ? rsqrtf((float)d) : 0.0f;
    }
}

// ---------------------------------------------------------------- CSR scatter, packed 8B record
__global__ void k_scatter(const int* __restrict__ row, const int* __restrict__ col) {
    int e = blockIdx.x * blockDim.x + threadIdx.x;
    if (e < NE) {
        int r = row[e];
        int c = col[e];
        int pos = atomicAdd(&g_cursor[r], 1);
        EdgeRec rec;
        rec.c = c;
        rec.n = g_dinv[r] * g_dinv[c];
        g_edge[pos] = rec;                  // single STG.64
    }
}

// ---------------------------------------------------------------- xl = x @ W^T + b  (f32x2 FMA, fp16 out)
#define BM 64
#define BK 32
__global__ __launch_bounds__(256) void k_gemm(const float* __restrict__ x,
                                              const float* __restrict__ W,
                                              const float* __restrict__ b) {
    __shared__ float Xs[BM][BK + 1];
    __shared__ float Wt[BK][132];

    int t  = threadIdx.x;
    int tx = t & 31;
    int ty = t >> 5;
    int row0 = blockIdx.x * BM;
    int n0 = tx * 4;

    unsigned long long acc[8][2];
#pragma unroll
    for (int i = 0; i < 8; i++) { acc[i][0] = 0ull; acc[i][1] = 0ull; }

    for (int k0 = 0; k0 < DD; k0 += BK) {
#pragma unroll
        for (int i = 0; i < 8; i++) {
            int m = ty + i * 8;
            int r = row0 + m;
            if (r >= NN) r = NN - 1;
            Xs[m][tx] = x[(size_t)r * DD + k0 + tx];
        }
#pragma unroll
        for (int i = 0; i < 16; i++) {
            int n = ty + i * 8;
            Wt[tx][n] = W[n * DD + k0 + tx];
        }
        __syncthreads();

#pragma unroll
        for (int kk = 0; kk < BK; kk++) {
            float4 wv = *(const float4*)&Wt[kk][n0];
            unsigned long long wxy, wzw;
            asm("mov.b64 %0, {%1, %2};" : "=l"(wxy) : "f"(wv.x), "f"(wv.y));
            asm("mov.b64 %0, {%1, %2};" : "=l"(wzw) : "f"(wv.z), "f"(wv.w));
#pragma unroll
            for (int i = 0; i < 8; i++) {
                float a = Xs[ty * 8 + i][kk];
                unsigned long long a2;
                asm("mov.b64 %0, {%1, %1};" : "=l"(a2) : "f"(a));
                asm("fma.rn.f32x2 %0, %1, %2, %0;" : "+l"(acc[i][0]) : "l"(a2), "l"(wxy));
                asm("fma.rn.f32x2 %0, %1, %2, %0;" : "+l"(acc[i][1]) : "l"(a2), "l"(wzw));
            }
        }
        __syncthreads();
    }

    float4 bias = *(const float4*)&b[n0];
#pragma unroll
    for (int i = 0; i < 8; i++) {
        int r = row0 + ty * 8 + i;
        if (r < NN) {
            float ax, ay, az, aw;
            asm("mov.b64 {%0, %1}, %2;" : "=f"(ax), "=f"(ay) : "l"(acc[i][0]));
            asm("mov.b64 {%0, %1}, %2;" : "=f"(az), "=f"(aw) : "l"(acc[i][1]));
            __half2 h0 = __floats2half2_rn(ax + bias.x, ay + bias.y);
            __half2 h1 = __floats2half2_rn(az + bias.z, aw + bias.w);
            uint2 o;
            o.x = *(unsigned int*)&h0;
            o.y = *(unsigned int*)&h1;
            *(uint2*)&g_xlh[(size_t)r * DD + n0] = o;   // 8B store, 8B aligned
        }
    }
}

// ---------------------------------------------------------------- warp-per-node aggregation (fp16 gather)
// Each lane owns 4 columns (lane*4..lane*4+3): loads uint2 = 4 halves per edge.
__global__ __launch_bounds__(256) void k_agg(float* __restrict__ out) {
    int wid  = (blockIdx.x * blockDim.x + threadIdx.x) >> 5;
    int lane = threadIdx.x & 31;
    if (wid >= NN) return;

    int s = g_start[wid];
    int d = g_deg[wid];

    float4 acc = make_float4(0.f, 0.f, 0.f, 0.f);
    const __half* xl = g_xlh;

    int j = 0;
    // align edge-record pointer to 16B for int4 loads
    if ((s & 1) && d > 0) {
        EdgeRec e = g_edge[s];
        uint2 p = *(const uint2*)&xl[(size_t)e.c * DD + lane * 4];
        float2 v0 = __half22float2(*(__half2*)&p.x);
        float2 v1 = __half22float2(*(__half2*)&p.y);
        acc.x += e.n * v0.x; acc.y += e.n * v0.y;
        acc.z += e.n * v1.x; acc.w += e.n * v1.y;
        j = 1;
    }
    const int4* ep = (const int4*)&g_edge[s + j];

    for (; j + 4 <= d; j += 4) {
        int4 p0 = __ldg(&ep[0]);
        int4 p1 = __ldg(&ep[1]);
        ep += 2;
        int   c0 = p0.x; float n0 = __int_as_float(p0.y);
        int   c1 = p0.z; float n1 = __int_as_float(p0.w);
        int   c2 = p1.x; float n2 = __int_as_float(p1.y);
        int   c3 = p1.z; float n3 = __int_as_float(p1.w);
        uint2 q0 = *(const uint2*)&xl[(size_t)c0 * DD + lane * 4];
        uint2 q1 = *(const uint2*)&xl[(size_t)c1 * DD + lane * 4];
        uint2 q2 = *(const uint2*)&xl[(size_t)c2 * DD + lane * 4];
        uint2 q3 = *(const uint2*)&xl[(size_t)c3 * DD + lane * 4];
        {
            float2 a = __half22float2(*(__half2*)&q0.x);
            float2 bb = __half22float2(*(__half2*)&q0.y);
            acc.x += n0 * a.x; acc.y += n0 * a.y; acc.z += n0 * bb.x; acc.w += n0 * bb.y;
        }
        {
            float2 a = __half22float2(*(__half2*)&q1.x);
            float2 bb = __half22float2(*(__half2*)&q1.y);
            acc.x += n1 * a.x; acc.y += n1 * a.y; acc.z += n1 * bb.x; acc.w += n1 * bb.y;
        }
        {
            float2 a = __half22float2(*(__half2*)&q2.x);
            float2 bb = __half22float2(*(__half2*)&q2.y);
            acc.x += n2 * a.x; acc.y += n2 * a.y; acc.z += n2 * bb.x; acc.w += n2 * bb.y;
        }
        {
            float2 a = __half22float2(*(__half2*)&q3.x);
            float2 bb = __half22float2(*(__half2*)&q3.y);
            acc.x += n3 * a.x; acc.y += n3 * a.y; acc.z += n3 * bb.x; acc.w += n3 * bb.y;
        }
    }
    for (; j < d; j++) {
        EdgeRec e = g_edge[s + j];
        uint2 p = *(const uint2*)&xl[(size_t)e.c * DD + lane * 4];
        float2 v0 = __half22float2(*(__half2*)&p.x);
        float2 v1 = __half22float2(*(__half2*)&p.y);
        acc.x += e.n * v0.x; acc.y += e.n * v0.y;
        acc.z += e.n * v1.x; acc.w += e.n * v1.y;
    }
    *(float4*)&out[(size_t)wid * DD + lane * 4] = acc;   // fully coalesced
}

// ---------------------------------------------------------------- stream fork for GEMM overlap
static cudaStream_t g_s2;
static cudaEvent_t  g_evFork, g_evJoin;
static struct StreamInit {
    StreamInit() {
        cudaStreamCreateWithFlags(&g_s2, cudaStreamNonBlocking);
        cudaEventCreateWithFlags(&g_evFork, cudaEventDisableTiming);
        cudaEventCreateWithFlags(&g_evJoin, cudaEventDisableTiming);
    }
} g_streamInit;

// ---------------------------------------------------------------- launch
extern "C" void kernel_launch(void* const* d_in, const int* in_sizes, int n_in,
                              void* d_out, int out_size) {
    const float* x  = (const float*)d_in[0];
    const int*   ei = (const int*)d_in[1];
    const float* W  = (const float*)d_in[2];
    const float* b  = (const float*)d_in[3];
    float* out = (float*)d_out;

    const int* row = ei;
    const int* col = ei + NE;

    // Fork: GEMM on side stream, CSR build on main stream, join before agg.
    cudaEventRecord(g_evFork, 0);
    cudaStreamWaitEvent(g_s2, g_evFork, 0);
    k_gemm<<<(NN + BM - 1) / BM, 256, 0, g_s2>>>(x, W, b);
    cudaEventRecord(g_evJoin, g_s2);

    k_zero   <<<(NN + 255) / 256, 256>>>();
    k_count  <<<(NE / 4 + 255) / 256, 256>>>(row);
    k_scan1  <<<NBLK, SCAN_B>>>();
    k_scan2  <<<1, 128>>>();
    k_scan3  <<<NBLK, SCAN_B>>>();
    k_scatter<<<(NE + 255) / 256, 256>>>(row, col);

    cudaStreamWaitEvent(0, g_evJoin, 0);
    k_agg    <<<((size_t)NN * 32 + 255) / 256, 256>>>(out);
}